// round 11
// baseline (speedup 1.0000x reference)
#include <cuda_runtime.h>
#include <cuda_fp16.h>
#include <cuda_fp8.h>
#include <cstdint>

#define BN 4
#define NN 4096
#define CC 256
#define DD 32
#define OUT_E (4*64*64*256)
#define PSCALE 4096.0f

// Scratch (device globals -> no allocations)
__device__ __half   g_qh [BN * NN * DD];
__device__ __half   g_kh [BN * NN * DD];
__device__ uint8_t  g_v8t[(long)BN * CC * NN];   // V transposed: [b][c][j], e4m3
__device__ float    g_s  [BN * NN];              // 1/rowsum

// ---------------------------------------------------------------------------
// helpers
// ---------------------------------------------------------------------------
__device__ __forceinline__ uint32_t smem_u32(const void* p) {
    return (uint32_t)__cvta_generic_to_shared(p);
}
__device__ __forceinline__ void ldsm4(uint32_t* r, uint32_t addr) {
    asm volatile("ldmatrix.sync.aligned.m8n8.x4.shared.b16 {%0,%1,%2,%3}, [%4];"
                 : "=r"(r[0]), "=r"(r[1]), "=r"(r[2]), "=r"(r[3]) : "r"(addr));
}
__device__ __forceinline__ void mma_f16(float* c, const uint32_t* a,
                                        uint32_t b0, uint32_t b1) {
    asm volatile("mma.sync.aligned.m16n8k16.row.col.f32.f16.f16.f32 "
                 "{%0,%1,%2,%3}, {%4,%5,%6,%7}, {%8,%9}, {%0,%1,%2,%3};"
                 : "+f"(c[0]), "+f"(c[1]), "+f"(c[2]), "+f"(c[3])
                 : "r"(a[0]), "r"(a[1]), "r"(a[2]), "r"(a[3]), "r"(b0), "r"(b1));
}
__device__ __forceinline__ void mma_f8(float* c, const uint32_t* a,
                                       uint32_t b0, uint32_t b1) {
    asm volatile("mma.sync.aligned.m16n8k32.row.col.f32.e4m3.e4m3.f32 "
                 "{%0,%1,%2,%3}, {%4,%5,%6,%7}, {%8,%9}, {%0,%1,%2,%3};"
                 : "+f"(c[0]), "+f"(c[1]), "+f"(c[2]), "+f"(c[3])
                 : "r"(a[0]), "r"(a[1]), "r"(a[2]), "r"(a[3]), "r"(b0), "r"(b1));
}
__device__ __forceinline__ unsigned short f2_to_e4m3x2(float lo, float hi) {
    return (unsigned short)__nv_cvt_float2_to_fp8x2(make_float2(lo, hi),
                                                    __NV_SATFINITE, __NV_E4M3);
}
#define CP16(dst, src) \
    asm volatile("cp.async.cg.shared.global [%0], [%1], 16;" :: "r"(dst), "l"(src))
#define CP_COMMIT() asm volatile("cp.async.commit_group;" ::: "memory")
#define CP_WAIT(n)  asm volatile("cp.async.wait_group %0;" :: "n"(n) : "memory")

// attn smem layout (bytes). All tile rows stride 80B -> conflict-free ldmatrix.
#define Q_OFF     0
#define P_OFF     5120
#define K2_OFF    15360
#define V_OFF     35840
#define SS_OFF    97792
#define SMEM_ATTN 98048
#define V_STAGE   20480
#define K2_STAGE  5120
#define P_BUF     5120

// ---------------------------------------------------------------------------
// Kernel 1: fused q,k,v projections via fp16 HMMA (unchanged from R10).
// ---------------------------------------------------------------------------
#define VK_X_OFF   0
#define VK_W_OFF   5120
#define VK_QK_OFF  25600
#define VK_T_OFF   5120
__global__ void __launch_bounds__(256, 2) qkv16_kernel(
    const float* __restrict__ x,
    const float* __restrict__ Wq, const float* __restrict__ bq,
    const float* __restrict__ Wk, const float* __restrict__ bk,
    const float* __restrict__ Wv, const float* __restrict__ bv)
{
    __shared__ __align__(16) char sm[30720];
    const uint32_t sb = smem_u32(sm);
    int row0 = blockIdx.x * 64;
    int tid  = threadIdx.x;
    int lane = tid & 31, warp = tid >> 5;
    int wm = warp & 1, wn = warp >> 1;

    float acc[2][8][4];
    float aqk[2][2][4];
#pragma unroll
    for (int mt = 0; mt < 2; mt++) {
#pragma unroll
        for (int nt = 0; nt < 8; nt++)
#pragma unroll
            for (int u = 0; u < 4; u++) acc[mt][nt][u] = 0.f;
#pragma unroll
        for (int nt = 0; nt < 2; nt++)
#pragma unroll
            for (int u = 0; u < 4; u++) aqk[mt][nt][u] = 0.f;
    }

    for (int kc = 0; kc < CC; kc += 32) {
        __syncthreads();
        {
            int r = tid >> 2, kq = (tid & 3) * 8;
            float4 xa = *(const float4*)&x[(long)(row0 + r) * CC + kc + kq];
            float4 xb = *(const float4*)&x[(long)(row0 + r) * CC + kc + kq + 4];
            __half2 h[4];
            h[0] = __floats2half2_rn(xa.x, xa.y);
            h[1] = __floats2half2_rn(xa.z, xa.w);
            h[2] = __floats2half2_rn(xb.x, xb.y);
            h[3] = __floats2half2_rn(xb.z, xb.w);
            *(uint4*)(sm + VK_X_OFF + r * 80 + kq * 2) = *(uint4*)h;
        }
#pragma unroll
        for (int p = 0; p < 32; p++) {
            int kk = p, n = tid;
            float wv_ = Wv[(long)(kc + kk) * CC + n];
            *(__half*)(sm + VK_W_OFF + n * 80 + kk * 2) = __float2half_rn(wv_);
        }
        {
            int n = tid & 63, kb = (tid >> 6) * 8;
#pragma unroll
            for (int k2 = 0; k2 < 8; k2++) {
                int kk = kb + k2;
                float wv_ = (n < 32) ? Wq[(long)(kc + kk) * DD + n]
                                     : Wk[(long)(kc + kk) * DD + (n - 32)];
                *(__half*)(sm + VK_QK_OFF + n * 80 + kk * 2) = __float2half_rn(wv_);
            }
        }
        __syncthreads();

        uint32_t af[2][2][4];
#pragma unroll
        for (int mt = 0; mt < 2; mt++) {
            uint32_t abase = sb + VK_X_OFF
                + (wm * 32 + mt * 16 + (lane & 7) + ((lane >> 3) & 1) * 8) * 80
                + (lane >> 4) * 16;
            ldsm4(af[mt][0], abase);
            ldsm4(af[mt][1], abase + 32);
        }
#pragma unroll
        for (int nt = 0; nt < 8; nt++) {
            uint32_t bf[4];
            uint32_t bbase = sb + VK_W_OFF
                + (wn * 64 + nt * 8 + (lane & 7)) * 80 + (lane >> 3) * 16;
            ldsm4(bf, bbase);
            mma_f16(acc[0][nt], af[0][0], bf[0], bf[1]);
            mma_f16(acc[0][nt], af[0][1], bf[2], bf[3]);
            mma_f16(acc[1][nt], af[1][0], bf[0], bf[1]);
            mma_f16(acc[1][nt], af[1][1], bf[2], bf[3]);
        }
#pragma unroll
        for (int nt = 0; nt < 2; nt++) {
            uint32_t bf[4];
            uint32_t bbase = sb + VK_QK_OFF
                + (wn * 16 + nt * 8 + (lane & 7)) * 80 + (lane >> 3) * 16;
            ldsm4(bf, bbase);
            mma_f16(aqk[0][nt], af[0][0], bf[0], bf[1]);
            mma_f16(aqk[0][nt], af[0][1], bf[2], bf[3]);
            mma_f16(aqk[1][nt], af[1][0], bf[0], bf[1]);
            mma_f16(aqk[1][nt], af[1][1], bf[2], bf[3]);
        }
    }

    // q/k epilogue
#pragma unroll
    for (int mt = 0; mt < 2; mt++) {
#pragma unroll
        for (int nt = 0; nt < 2; nt++) {
            int r = wm * 32 + mt * 16 + (lane >> 2);
            int gcol = wn * 16 + nt * 8 + ((lane & 3) << 1);
            int isq = gcol < 32;
            int cc = isq ? gcol : gcol - 32;
            const float* bb_ = isq ? bq : bk;
            __half* dst = isq ? g_qh : g_kh;
            float b0 = bb_[cc], b1 = bb_[cc + 1];
            *(__half2*)&dst[(long)(row0 + r) * DD + cc] =
                __floats2half2_rn(aqk[mt][nt][0] + b0, aqk[mt][nt][1] + b1);
            *(__half2*)&dst[(long)(row0 + r + 8) * DD + cc] =
                __floats2half2_rn(aqk[mt][nt][2] + b0, aqk[mt][nt][3] + b1);
        }
    }

    __syncthreads();

    uint8_t* t8 = (uint8_t*)(sm + VK_T_OFF);
#pragma unroll
    for (int mt = 0; mt < 2; mt++) {
        int r = wm * 32 + mt * 16 + (lane >> 2);
#pragma unroll
        for (int nt = 0; nt < 8; nt++) {
            int c = wn * 64 + nt * 8 + ((lane & 3) << 1);
            float b0 = bv[c], b1 = bv[c + 1];
            unsigned short pa = f2_to_e4m3x2(acc[mt][nt][0] + b0, acc[mt][nt][1] + b1);
            unsigned short pb = f2_to_e4m3x2(acc[mt][nt][2] + b0, acc[mt][nt][3] + b1);
            t8[c * 80 + r]           = (uint8_t)(pa & 0xff);
            t8[(c + 1) * 80 + r]     = (uint8_t)(pa >> 8);
            t8[c * 80 + r + 8]       = (uint8_t)(pb & 0xff);
            t8[(c + 1) * 80 + r + 8] = (uint8_t)(pb >> 8);
        }
    }
    __syncthreads();

    int bb = row0 / NN;
    int jj = row0 % NN;
    uint8_t* vt = g_v8t + (long)bb * CC * NN;
#pragma unroll
    for (int p = 0; p < 4; p++) {
        int e = tid + p * 256;
        int c = e >> 2, j16 = (e & 3) * 16;
        uint4 v4 = *(uint4*)(sm + VK_T_OFF + c * 80 + j16);
        *(uint4*)&vt[(long)c * NN + jj + j16] = v4;
    }
}

// ---------------------------------------------------------------------------
// Kernel 2: row sums of exp(Q.K^T) -> g_s = 1/s.  High-occupancy, low-reg.
//  32 i-rows per CTA, 128 threads (4 warps, warp w = j-slice), JT=128, 3-stage.
// ---------------------------------------------------------------------------
#define SK_Q_OFF  0                       // 32 x 80
#define SK_K_OFF  2560                    // 3 stages x 128 x 80
#define SK_KSTG   10240
#define SK_SR_OFF (2560 + 3*10240)        // 33280: 32 x 4 f32
__global__ void __launch_bounds__(128) sum_kernel()
{
    __shared__ __align__(16) char sm[33792];
    const uint32_t sb = smem_u32(sm);
    int tid = threadIdx.x, lane = tid & 31, w = tid >> 5;
    int b = blockIdx.y, i0 = blockIdx.x * 32;
    const __half* qg = g_qh + ((long)b * NN + i0) * DD;
    const __half* kg = g_kh + (long)b * NN * DD;

    // Q tile (32 rows x 64B)
    {
        int r = tid >> 2, ch = tid & 3;
        *(uint4*)(sm + SK_Q_OFF + r * 80 + ch * 16) = *(const uint4*)(qg + r * DD + ch * 8);
    }
    // K stage 0
    {
        uint32_t kst = sb + SK_K_OFF;
#pragma unroll
        for (int p = 0; p < 4; p++) {
            int idx = tid + p * 128;
            int r = idx >> 2, ch = idx & 3;
            CP16(kst + r * 80 + ch * 16, kg + r * DD + ch * 8);
        }
        CP_COMMIT();
    }
    __syncthreads();

    uint32_t qf[2][2][4];
#pragma unroll
    for (int mt = 0; mt < 2; mt++) {
        uint32_t base = sb + SK_Q_OFF
            + (mt * 16 + (lane & 7) + ((lane >> 3) & 1) * 8) * 80 + (lane >> 4) * 16;
        ldsm4(qf[mt][0], base);
        ldsm4(qf[mt][1], base + 32);
    }

    float s[4] = {0.f, 0.f, 0.f, 0.f};
    for (int t = 0; t < 32; t++) {
        if (t + 1 < 32) {
            uint32_t kst = sb + SK_K_OFF + ((t + 1) % 3) * SK_KSTG;
            const __half* src = kg + (t + 1) * 128 * DD;
#pragma unroll
            for (int p = 0; p < 4; p++) {
                int idx = tid + p * 128;
                int r = idx >> 2, ch = idx & 3;
                CP16(kst + r * 80 + ch * 16, src + r * DD + ch * 8);
            }
        }
        CP_COMMIT();
        CP_WAIT(1);
        __syncthreads();

        uint32_t kst = sb + SK_K_OFF + (t % 3) * SK_KSTG;
        uint32_t bbase = kst + (w * 32 + (lane & 7)) * 80 + (lane >> 3) * 16;
#pragma unroll
        for (int nt = 0; nt < 4; nt++) {
            uint32_t bf[4];
            ldsm4(bf, bbase + nt * 8 * 80);
#pragma unroll
            for (int mt = 0; mt < 2; mt++) {
                float c[4] = {0.f, 0.f, 0.f, 0.f};
                mma_f16(c, qf[mt][0], bf[0], bf[1]);
                mma_f16(c, qf[mt][1], bf[2], bf[3]);
                s[mt * 2]     += __expf(c[0]) + __expf(c[1]);
                s[mt * 2 + 1] += __expf(c[2]) + __expf(c[3]);
            }
        }
    }
#pragma unroll
    for (int k = 0; k < 4; k++) {
        s[k] += __shfl_xor_sync(0xffffffffu, s[k], 1);
        s[k] += __shfl_xor_sync(0xffffffffu, s[k], 2);
    }
    float* sred = (float*)(sm + SK_SR_OFF);
    if ((lane & 3) == 0) {
        int r0 = lane >> 2;
        sred[(r0     ) * 4 + w] = s[0];
        sred[(r0 + 8 ) * 4 + w] = s[1];
        sred[(r0 + 16) * 4 + w] = s[2];
        sred[(r0 + 24) * 4 + w] = s[3];
    }
    __syncthreads();
    if (tid < 32) {
        float tot = sred[tid * 4] + sred[tid * 4 + 1] + sred[tid * 4 + 2] + sred[tid * 4 + 3];
        g_s[b * NN + i0 + tid] = 1.0f / tot;
    }
}

// ---------------------------------------------------------------------------
// Kernel 3: attention pass2-only (reads 1/s from g_s); pipelined as R10.
// ---------------------------------------------------------------------------
__global__ void __launch_bounds__(256, 2) attn_kernel(
    const float* __restrict__ x, const float* __restrict__ gamma,
    float* __restrict__ att_out, float* __restrict__ y)
{
    extern __shared__ __align__(16) char smem[];
    const uint32_t sb = smem_u32(smem);
    const int tid  = threadIdx.x;
    const int lane = tid & 31, w = tid >> 5;
    const int wi = w & 3, wj = w >> 2;
    const int avi = w & 1, avc = w >> 1;

    const int b  = blockIdx.y;
    const int i0 = blockIdx.x * 64;

    const __half*  qg  = g_qh + ((long)b * NN + i0) * DD;
    const __half*  kg  = g_kh + (long)b * NN * DD;
    const uint8_t* vtg = g_v8t + (long)b * CC * NN;

    // Q tile -> smem; inverse sums -> smem
    {
        int r = tid >> 2, ch = tid & 3;
        *(uint4*)(smem + Q_OFF + r * 80 + ch * 16) =
            *(const uint4*)(qg + r * DD + ch * 8);
    }
    if (tid < 64)
        ((float*)(smem + SS_OFF))[tid] = g_s[(long)b * NN + i0 + tid];

    // prolog prefetch: {V(0), K2(0)} then {K2(1)}
    {
        uint32_t vst = sb + V_OFF;
#pragma unroll
        for (int p = 0; p < 4; p++) {
            int idx = tid + p * 256;
            int c = idx >> 2, ch = idx & 3;
            CP16(vst + c * 80 + ch * 16, vtg + (long)c * NN + ch * 16);
        }
        int r = tid >> 2, ch = tid & 3;
        CP16(sb + K2_OFF + r * 80 + ch * 16, kg + r * DD + ch * 8);
        CP_COMMIT();
        CP16(sb + K2_OFF + K2_STAGE + r * 80 + ch * 16, kg + (64 + r) * DD + ch * 8);
        CP_COMMIT();
    }
    __syncthreads();

    uint32_t qf[2][4];
    {
        uint32_t base = sb + Q_OFF
            + (wi * 16 + (lane & 7) + ((lane >> 3) & 1) * 8) * 80
            + (lane >> 4) * 16;
        ldsm4(qf[0], base);
        ldsm4(qf[1], base + 32);
    }
    const float is0 = ((const float*)(smem + SS_OFF))[wi * 16 + (lane >> 2)];
    const float is1 = ((const float*)(smem + SS_OFF))[wi * 16 + (lane >> 2) + 8];

    // =========================== PASS 2 (pipelined) ========================
    float acc[2][8][4];
#pragma unroll
    for (int mt = 0; mt < 2; mt++)
#pragma unroll
        for (int nt = 0; nt < 8; nt++)
#pragma unroll
            for (int u = 0; u < 4; u++) acc[mt][nt][u] = 0.f;

    float* ab = att_out ? att_out + ((long)b * NN + i0) * NN : (float*)0;
    const int er0 = wi * 16 + (lane >> 2);
    int vs_r = 0;
    int vs_w = 1;

    for (int t = 0; t <= 64; t++) {
        CP_WAIT(1);
        __syncthreads();

        if (t < 64) {
            const int j0 = t * 64;
            uint32_t k2t = sb + K2_OFF + (t & 3) * K2_STAGE;
            uint32_t ebase = k2t + (wj * 32 + (lane & 7)) * 80 + (lane >> 3) * 16;
            const int pw = P_OFF + (t & 1) * P_BUF;
#pragma unroll
            for (int nt = 0; nt < 4; nt++) {
                uint32_t bf[4];
                ldsm4(bf, ebase + nt * 8 * 80);
                float c[4] = {0.f, 0.f, 0.f, 0.f};
                mma_f16(c, qf[0], bf[0], bf[1]);
                mma_f16(c, qf[1], bf[2], bf[3]);
                float a0 = __expf(c[0]) * is0, a1 = __expf(c[1]) * is0;
                float a2 = __expf(c[2]) * is1, a3 = __expf(c[3]) * is1;
                int col = wj * 32 + nt * 8 + ((lane & 3) << 1);
                *(unsigned short*)(smem + pw + er0 * 80 + col) =
                    f2_to_e4m3x2(a0 * PSCALE, a1 * PSCALE);
                *(unsigned short*)(smem + pw + (er0 + 8) * 80 + col) =
                    f2_to_e4m3x2(a2 * PSCALE, a3 * PSCALE);
                if (ab) {
                    *(float2*)&ab[(long)er0 * NN + j0 + col]       = make_float2(a0, a1);
                    *(float2*)&ab[(long)(er0 + 8) * NN + j0 + col] = make_float2(a2, a3);
                }
            }
        }

        if (t > 0) {
            uint32_t vst = sb + V_OFF + vs_r * V_STAGE;
            uint32_t pA  = sb + P_OFF + ((t - 1) & 1) * P_BUF
                + (avi * 32 + (lane & 7) + ((lane >> 3) & 1) * 8) * 80
                + ((lane >> 4) & 1) * 16;
            uint32_t af[2][2][4];
#pragma unroll
            for (int mt = 0; mt < 2; mt++) {
                ldsm4(af[mt][0], pA + mt * 16 * 80);
                ldsm4(af[mt][1], pA + mt * 16 * 80 + 32);
            }
#pragma unroll
            for (int kk = 0; kk < 2; kk++) {
#pragma unroll
                for (int ntg = 0; ntg < 4; ntg++) {
                    uint32_t bv[4];
                    uint32_t baddr = vst
                        + (avc * 64 + ntg * 16 + (lane & 7) + ((lane >> 4) & 1) * 8) * 80
                        + ((lane >> 3) & 1) * 16 + kk * 32;
                    ldsm4(bv, baddr);
                    mma_f8(acc[0][ntg * 2],     af[0][kk], bv[0], bv[1]);
                    mma_f8(acc[0][ntg * 2 + 1], af[0][kk], bv[2], bv[3]);
                    mma_f8(acc[1][ntg * 2],     af[1][kk], bv[0], bv[1]);
                    mma_f8(acc[1][ntg * 2 + 1], af[1][kk], bv[2], bv[3]);
                }
            }
            vs_r = (vs_r == 2) ? 0 : vs_r + 1;
        }

        if (t <= 62) {
            uint32_t vst = sb + V_OFF + vs_w * V_STAGE;
            const uint8_t* vsrc = vtg + (t + 1) * 64;
#pragma unroll
            for (int p = 0; p < 4; p++) {
                int idx = tid + p * 256;
                int c = idx >> 2, ch = idx & 3;
                CP16(vst + c * 80 + ch * 16, vsrc + (long)c * NN + ch * 16);
            }
            vs_w = (vs_w == 2) ? 0 : vs_w + 1;
        }
        if (t <= 61) {
            uint32_t k2t = sb + K2_OFF + ((t + 2) & 3) * K2_STAGE;
            const __half* ksrc = kg + (t + 2) * 64 * DD;
            int r = tid >> 2, ch = tid & 3;
            CP16(k2t + r * 80 + ch * 16, ksrc + r * DD + ch * 8);
        }
        CP_COMMIT();
    }

    // ---- epilogue: y = acc*(gamma/PSCALE) + x ----
    const float g = gamma[0] * (1.0f / PSCALE);
    const float* xb = x + ((long)b * NN + i0) * CC;
    float* yb = y + ((long)b * NN + i0) * CC;
#pragma unroll
    for (int mt = 0; mt < 2; mt++) {
        int r0 = avi * 32 + mt * 16 + (lane >> 2);
#pragma unroll
        for (int nt = 0; nt < 8; nt++) {
            int c = avc * 64 + nt * 8 + ((lane & 3) << 1);
            float2 x0 = *(const float2*)&xb[(long)r0 * CC + c];
            float2 x1 = *(const float2*)&xb[(long)(r0 + 8) * CC + c];
            float2 o0, o1;
            o0.x = acc[mt][nt][0] * g + x0.x;  o0.y = acc[mt][nt][1] * g + x0.y;
            o1.x = acc[mt][nt][2] * g + x1.x;  o1.y = acc[mt][nt][3] * g + x1.y;
            *(float2*)&yb[(long)r0 * CC + c]       = o0;
            *(float2*)&yb[(long)(r0 + 8) * CC + c] = o1;
        }
    }
}

// ---------------------------------------------------------------------------
extern "C" void kernel_launch(void* const* d_in, const int* in_sizes, int n_in,
                              void* d_out, int out_size)
{
    const float* x     = (const float*)d_in[0];
    const float* Wq    = (const float*)d_in[1];
    const float* bq    = (const float*)d_in[2];
    const float* Wk    = (const float*)d_in[3];
    const float* bk    = (const float*)d_in[4];
    const float* Wv    = (const float*)d_in[5];
    const float* bv    = (const float*)d_in[6];
    const float* gamma = (const float*)d_in[7];
    float* y = (float*)d_out;

    const long ATT_E = (long)BN * NN * NN;
    float* att_out = 0;
    if ((long)out_size == (long)OUT_E + ATT_E) att_out = y + OUT_E;

    cudaFuncSetAttribute(attn_kernel, cudaFuncAttributeMaxDynamicSharedMemorySize,
                         SMEM_ATTN);

    qkv16_kernel<<<BN * NN / 64, 256>>>(x, Wq, bq, Wk, bk, Wv, bv);
    sum_kernel<<<dim3(NN / 32, BN), 128>>>();
    attn_kernel<<<dim3(NN / 64, BN), 256, SMEM_ATTN>>>(x, gamma, att_out, y);
}

// round 12
// speedup vs baseline: 1.0372x; 1.0372x over previous
#include <cuda_runtime.h>
#include <cuda_fp16.h>
#include <cuda_fp8.h>
#include <cstdint>

#define BN 4
#define NN 4096
#define CC 256
#define DD 32
#define OUT_E (4*64*64*256)
#define PSCALE 4096.0f

// Scratch (device globals -> no allocations)
__device__ __half   g_qh [BN * NN * DD];
__device__ __half   g_kh [BN * NN * DD];
__device__ uint8_t  g_v8t[(long)BN * CC * NN];   // V transposed: [b][c][j], e4m3
__device__ float    g_s  [BN * NN];              // 1/rowsum

// ---------------------------------------------------------------------------
// helpers
// ---------------------------------------------------------------------------
__device__ __forceinline__ uint32_t smem_u32(const void* p) {
    return (uint32_t)__cvta_generic_to_shared(p);
}
__device__ __forceinline__ void ldsm4(uint32_t* r, uint32_t addr) {
    asm volatile("ldmatrix.sync.aligned.m8n8.x4.shared.b16 {%0,%1,%2,%3}, [%4];"
                 : "=r"(r[0]), "=r"(r[1]), "=r"(r[2]), "=r"(r[3]) : "r"(addr));
}
__device__ __forceinline__ void mma_f16(float* c, const uint32_t* a,
                                        uint32_t b0, uint32_t b1) {
    asm volatile("mma.sync.aligned.m16n8k16.row.col.f32.f16.f16.f32 "
                 "{%0,%1,%2,%3}, {%4,%5,%6,%7}, {%8,%9}, {%0,%1,%2,%3};"
                 : "+f"(c[0]), "+f"(c[1]), "+f"(c[2]), "+f"(c[3])
                 : "r"(a[0]), "r"(a[1]), "r"(a[2]), "r"(a[3]), "r"(b0), "r"(b1));
}
__device__ __forceinline__ void mma_f8(float* c, const uint32_t* a,
                                       uint32_t b0, uint32_t b1) {
    asm volatile("mma.sync.aligned.m16n8k32.row.col.f32.e4m3.e4m3.f32 "
                 "{%0,%1,%2,%3}, {%4,%5,%6,%7}, {%8,%9}, {%0,%1,%2,%3};"
                 : "+f"(c[0]), "+f"(c[1]), "+f"(c[2]), "+f"(c[3])
                 : "r"(a[0]), "r"(a[1]), "r"(a[2]), "r"(a[3]), "r"(b0), "r"(b1));
}
__device__ __forceinline__ unsigned short f2_to_e4m3x2(float lo, float hi) {
    return (unsigned short)__nv_cvt_float2_to_fp8x2(make_float2(lo, hi),
                                                    __NV_SATFINITE, __NV_E4M3);
}
#define CP16(dst, src) \
    asm volatile("cp.async.cg.shared.global [%0], [%1], 16;" :: "r"(dst), "l"(src))
#define CP_COMMIT() asm volatile("cp.async.commit_group;" ::: "memory")
#define CP_WAIT(n)  asm volatile("cp.async.wait_group %0;" :: "n"(n) : "memory")

// attn smem layout (bytes).
#define Q_OFF     0                      // 64 x 80
#define P_OFF     5120                   // 64 x 80 (single buffer, fp8)
#define K2_OFF    10240                  // 4 stages x 64 x 80 (fp16)
#define V_OFF     30720                  // 3 stages x 256 x 80 (fp8)
#define ATT_OFF   92160                  // 64 x 72 f32 = 18432
#define SS_OFF    110592                 // 64 f32
#define SMEM_ATTN 110848
#define V_STAGE   20480
#define K2_STAGE  5120
#define ATT_STRIDE 72                    // f32; 72 mod 32 = 8 -> conflict-free

// ---------------------------------------------------------------------------
// Kernel 1: fused q,k,v projections via fp16 HMMA (unchanged from R10/R11).
// ---------------------------------------------------------------------------
#define VK_X_OFF   0
#define VK_W_OFF   5120
#define VK_QK_OFF  25600
#define VK_T_OFF   5120
__global__ void __launch_bounds__(256, 2) qkv16_kernel(
    const float* __restrict__ x,
    const float* __restrict__ Wq, const float* __restrict__ bq,
    const float* __restrict__ Wk, const float* __restrict__ bk,
    const float* __restrict__ Wv, const float* __restrict__ bv)
{
    __shared__ __align__(16) char sm[30720];
    const uint32_t sb = smem_u32(sm);
    int row0 = blockIdx.x * 64;
    int tid  = threadIdx.x;
    int lane = tid & 31, warp = tid >> 5;
    int wm = warp & 1, wn = warp >> 1;

    float acc[2][8][4];
    float aqk[2][2][4];
#pragma unroll
    for (int mt = 0; mt < 2; mt++) {
#pragma unroll
        for (int nt = 0; nt < 8; nt++)
#pragma unroll
            for (int u = 0; u < 4; u++) acc[mt][nt][u] = 0.f;
#pragma unroll
        for (int nt = 0; nt < 2; nt++)
#pragma unroll
            for (int u = 0; u < 4; u++) aqk[mt][nt][u] = 0.f;
    }

    for (int kc = 0; kc < CC; kc += 32) {
        __syncthreads();
        {
            int r = tid >> 2, kq = (tid & 3) * 8;
            float4 xa = *(const float4*)&x[(long)(row0 + r) * CC + kc + kq];
            float4 xb = *(const float4*)&x[(long)(row0 + r) * CC + kc + kq + 4];
            __half2 h[4];
            h[0] = __floats2half2_rn(xa.x, xa.y);
            h[1] = __floats2half2_rn(xa.z, xa.w);
            h[2] = __floats2half2_rn(xb.x, xb.y);
            h[3] = __floats2half2_rn(xb.z, xb.w);
            *(uint4*)(sm + VK_X_OFF + r * 80 + kq * 2) = *(uint4*)h;
        }
#pragma unroll
        for (int p = 0; p < 32; p++) {
            int kk = p, n = tid;
            float wv_ = Wv[(long)(kc + kk) * CC + n];
            *(__half*)(sm + VK_W_OFF + n * 80 + kk * 2) = __float2half_rn(wv_);
        }
        {
            int n = tid & 63, kb = (tid >> 6) * 8;
#pragma unroll
            for (int k2 = 0; k2 < 8; k2++) {
                int kk = kb + k2;
                float wv_ = (n < 32) ? Wq[(long)(kc + kk) * DD + n]
                                     : Wk[(long)(kc + kk) * DD + (n - 32)];
                *(__half*)(sm + VK_QK_OFF + n * 80 + kk * 2) = __float2half_rn(wv_);
            }
        }
        __syncthreads();

        uint32_t af[2][2][4];
#pragma unroll
        for (int mt = 0; mt < 2; mt++) {
            uint32_t abase = sb + VK_X_OFF
                + (wm * 32 + mt * 16 + (lane & 7) + ((lane >> 3) & 1) * 8) * 80
                + (lane >> 4) * 16;
            ldsm4(af[mt][0], abase);
            ldsm4(af[mt][1], abase + 32);
        }
#pragma unroll
        for (int nt = 0; nt < 8; nt++) {
            uint32_t bf[4];
            uint32_t bbase = sb + VK_W_OFF
                + (wn * 64 + nt * 8 + (lane & 7)) * 80 + (lane >> 3) * 16;
            ldsm4(bf, bbase);
            mma_f16(acc[0][nt], af[0][0], bf[0], bf[1]);
            mma_f16(acc[0][nt], af[0][1], bf[2], bf[3]);
            mma_f16(acc[1][nt], af[1][0], bf[0], bf[1]);
            mma_f16(acc[1][nt], af[1][1], bf[2], bf[3]);
        }
#pragma unroll
        for (int nt = 0; nt < 2; nt++) {
            uint32_t bf[4];
            uint32_t bbase = sb + VK_QK_OFF
                + (wn * 16 + nt * 8 + (lane & 7)) * 80 + (lane >> 3) * 16;
            ldsm4(bf, bbase);
            mma_f16(aqk[0][nt], af[0][0], bf[0], bf[1]);
            mma_f16(aqk[0][nt], af[0][1], bf[2], bf[3]);
            mma_f16(aqk[1][nt], af[1][0], bf[0], bf[1]);
            mma_f16(aqk[1][nt], af[1][1], bf[2], bf[3]);
        }
    }

    // q/k epilogue
#pragma unroll
    for (int mt = 0; mt < 2; mt++) {
#pragma unroll
        for (int nt = 0; nt < 2; nt++) {
            int r = wm * 32 + mt * 16 + (lane >> 2);
            int gcol = wn * 16 + nt * 8 + ((lane & 3) << 1);
            int isq = gcol < 32;
            int cc = isq ? gcol : gcol - 32;
            const float* bb_ = isq ? bq : bk;
            __half* dst = isq ? g_qh : g_kh;
            float b0 = bb_[cc], b1 = bb_[cc + 1];
            *(__half2*)&dst[(long)(row0 + r) * DD + cc] =
                __floats2half2_rn(aqk[mt][nt][0] + b0, aqk[mt][nt][1] + b1);
            *(__half2*)&dst[(long)(row0 + r + 8) * DD + cc] =
                __floats2half2_rn(aqk[mt][nt][2] + b0, aqk[mt][nt][3] + b1);
        }
    }

    __syncthreads();

    uint8_t* t8 = (uint8_t*)(sm + VK_T_OFF);
#pragma unroll
    for (int mt = 0; mt < 2; mt++) {
        int r = wm * 32 + mt * 16 + (lane >> 2);
#pragma unroll
        for (int nt = 0; nt < 8; nt++) {
            int c = wn * 64 + nt * 8 + ((lane & 3) << 1);
            float b0 = bv[c], b1 = bv[c + 1];
            unsigned short pa = f2_to_e4m3x2(acc[mt][nt][0] + b0, acc[mt][nt][1] + b1);
            unsigned short pb = f2_to_e4m3x2(acc[mt][nt][2] + b0, acc[mt][nt][3] + b1);
            t8[c * 80 + r]           = (uint8_t)(pa & 0xff);
            t8[(c + 1) * 80 + r]     = (uint8_t)(pa >> 8);
            t8[c * 80 + r + 8]       = (uint8_t)(pb & 0xff);
            t8[(c + 1) * 80 + r + 8] = (uint8_t)(pb >> 8);
        }
    }
    __syncthreads();

    int bb = row0 / NN;
    int jj = row0 % NN;
    uint8_t* vt = g_v8t + (long)bb * CC * NN;
#pragma unroll
    for (int p = 0; p < 4; p++) {
        int e = tid + p * 256;
        int c = e >> 2, j16 = (e & 3) * 16;
        uint4 v4 = *(uint4*)(sm + VK_T_OFF + c * 80 + j16);
        *(uint4*)&vt[(long)c * NN + jj + j16] = v4;
    }
}

// ---------------------------------------------------------------------------
// Kernel 2: row sums of exp(Q.K^T) -> g_s = 1/s (unchanged from R11).
// ---------------------------------------------------------------------------
#define SK_Q_OFF  0
#define SK_K_OFF  2560
#define SK_KSTG   10240
#define SK_SR_OFF (2560 + 3*10240)
__global__ void __launch_bounds__(128) sum_kernel()
{
    __shared__ __align__(16) char sm[33792];
    const uint32_t sb = smem_u32(sm);
    int tid = threadIdx.x, lane = tid & 31, w = tid >> 5;
    int b = blockIdx.y, i0 = blockIdx.x * 32;
    const __half* qg = g_qh + ((long)b * NN + i0) * DD;
    const __half* kg = g_kh + (long)b * NN * DD;

    {
        int r = tid >> 2, ch = tid & 3;
        *(uint4*)(sm + SK_Q_OFF + r * 80 + ch * 16) = *(const uint4*)(qg + r * DD + ch * 8);
    }
    {
        uint32_t kst = sb + SK_K_OFF;
#pragma unroll
        for (int p = 0; p < 4; p++) {
            int idx = tid + p * 128;
            int r = idx >> 2, ch = idx & 3;
            CP16(kst + r * 80 + ch * 16, kg + r * DD + ch * 8);
        }
        CP_COMMIT();
    }
    __syncthreads();

    uint32_t qf[2][2][4];
#pragma unroll
    for (int mt = 0; mt < 2; mt++) {
        uint32_t base = sb + SK_Q_OFF
            + (mt * 16 + (lane & 7) + ((lane >> 3) & 1) * 8) * 80 + (lane >> 4) * 16;
        ldsm4(qf[mt][0], base);
        ldsm4(qf[mt][1], base + 32);
    }

    float s[4] = {0.f, 0.f, 0.f, 0.f};
    for (int t = 0; t < 32; t++) {
        if (t + 1 < 32) {
            uint32_t kst = sb + SK_K_OFF + ((t + 1) % 3) * SK_KSTG;
            const __half* src = kg + (t + 1) * 128 * DD;
#pragma unroll
            for (int p = 0; p < 4; p++) {
                int idx = tid + p * 128;
                int r = idx >> 2, ch = idx & 3;
                CP16(kst + r * 80 + ch * 16, src + r * DD + ch * 8);
            }
        }
        CP_COMMIT();
        CP_WAIT(1);
        __syncthreads();

        uint32_t kst = sb + SK_K_OFF + (t % 3) * SK_KSTG;
        uint32_t bbase = kst + (w * 32 + (lane & 7)) * 80 + (lane >> 3) * 16;
#pragma unroll
        for (int nt = 0; nt < 4; nt++) {
            uint32_t bf[4];
            ldsm4(bf, bbase + nt * 8 * 80);
#pragma unroll
            for (int mt = 0; mt < 2; mt++) {
                float c[4] = {0.f, 0.f, 0.f, 0.f};
                mma_f16(c, qf[mt][0], bf[0], bf[1]);
                mma_f16(c, qf[mt][1], bf[2], bf[3]);
                s[mt * 2]     += __expf(c[0]) + __expf(c[1]);
                s[mt * 2 + 1] += __expf(c[2]) + __expf(c[3]);
            }
        }
    }
#pragma unroll
    for (int k = 0; k < 4; k++) {
        s[k] += __shfl_xor_sync(0xffffffffu, s[k], 1);
        s[k] += __shfl_xor_sync(0xffffffffu, s[k], 2);
    }
    float* sred = (float*)(sm + SK_SR_OFF);
    if ((lane & 3) == 0) {
        int r0 = lane >> 2;
        sred[(r0     ) * 4 + w] = s[0];
        sred[(r0 + 8 ) * 4 + w] = s[1];
        sred[(r0 + 16) * 4 + w] = s[2];
        sred[(r0 + 24) * 4 + w] = s[3];
    }
    __syncthreads();
    if (tid < 32) {
        float tot = sred[tid * 4] + sred[tid * 4 + 1] + sred[tid * 4 + 2] + sred[tid * 4 + 3];
        g_s[b * NN + i0 + tid] = 1.0f / tot;
    }
}

// ---------------------------------------------------------------------------
// Kernel 3: attention pass2-only. att staged in smem -> coalesced STG.128.
//  iter t: E(t)->exp->{P fp8, att_s f32}; sync; att STG + AV(t); prefetch t+2
// ---------------------------------------------------------------------------
__global__ void __launch_bounds__(256, 2) attn_kernel(
    const float* __restrict__ x, const float* __restrict__ gamma,
    float* __restrict__ att_out, float* __restrict__ y)
{
    extern __shared__ __align__(16) char smem[];
    const uint32_t sb = smem_u32(smem);
    const int tid  = threadIdx.x;
    const int lane = tid & 31, w = tid >> 5;
    const int wi = w & 3, wj = w >> 2;
    const int avi = w & 1, avc = w >> 1;

    const int b  = blockIdx.y;
    const int i0 = blockIdx.x * 64;

    const __half*  qg  = g_qh + ((long)b * NN + i0) * DD;
    const __half*  kg  = g_kh + (long)b * NN * DD;
    const uint8_t* vtg = g_v8t + (long)b * CC * NN;

    // Q tile + inverse sums
    {
        int r = tid >> 2, ch = tid & 3;
        *(uint4*)(smem + Q_OFF + r * 80 + ch * 16) =
            *(const uint4*)(qg + r * DD + ch * 8);
    }
    if (tid < 64)
        ((float*)(smem + SS_OFF))[tid] = g_s[(long)b * NN + i0 + tid];

    // prolog prefetch: group{V(0),K2(0)}, group{V(1),K2(1)}
    {
#pragma unroll
        for (int st = 0; st < 2; st++) {
            uint32_t vst = sb + V_OFF + st * V_STAGE;
            const uint8_t* vsrc = vtg + st * 64;
#pragma unroll
            for (int p = 0; p < 4; p++) {
                int idx = tid + p * 256;
                int c = idx >> 2, ch = idx & 3;
                CP16(vst + c * 80 + ch * 16, vsrc + (long)c * NN + ch * 16);
            }
            int r = tid >> 2, ch = tid & 3;
            CP16(sb + K2_OFF + st * K2_STAGE + r * 80 + ch * 16,
                 kg + (st * 64 + r) * DD + ch * 8);
            CP_COMMIT();
        }
    }
    __syncthreads();

    uint32_t qf[2][4];
    {
        uint32_t base = sb + Q_OFF
            + (wi * 16 + (lane & 7) + ((lane >> 3) & 1) * 8) * 80
            + (lane >> 4) * 16;
        ldsm4(qf[0], base);
        ldsm4(qf[1], base + 32);
    }
    const float is0 = ((const float*)(smem + SS_OFF))[wi * 16 + (lane >> 2)];
    const float is1 = ((const float*)(smem + SS_OFF))[wi * 16 + (lane >> 2) + 8];

    float acc[2][8][4];
#pragma unroll
    for (int mt = 0; mt < 2; mt++)
#pragma unroll
        for (int nt = 0; nt < 8; nt++)
#pragma unroll
            for (int u = 0; u < 4; u++) acc[mt][nt][u] = 0.f;

    float* ab = att_out ? att_out + ((long)b * NN + i0) * NN : (float*)0;
    const int er0 = wi * 16 + (lane >> 2);
    float* att_s = (float*)(smem + ATT_OFF);

    for (int t = 0; t < 64; t++) {
        const int j0 = t * 64;
        CP_WAIT(1);
        __syncthreads();

        // ---- E(t) -> exp -> {P fp8, att_s f32} ----
        {
            uint32_t k2t = sb + K2_OFF + (t & 3) * K2_STAGE;
            uint32_t ebase = k2t + (wj * 32 + (lane & 7)) * 80 + (lane >> 3) * 16;
#pragma unroll
            for (int nt = 0; nt < 4; nt++) {
                uint32_t bf[4];
                ldsm4(bf, ebase + nt * 8 * 80);
                float c[4] = {0.f, 0.f, 0.f, 0.f};
                mma_f16(c, qf[0], bf[0], bf[1]);
                mma_f16(c, qf[1], bf[2], bf[3]);
                float a0 = __expf(c[0]) * is0, a1 = __expf(c[1]) * is0;
                float a2 = __expf(c[2]) * is1, a3 = __expf(c[3]) * is1;
                int col = wj * 32 + nt * 8 + ((lane & 3) << 1);
                *(unsigned short*)(smem + P_OFF + er0 * 80 + col) =
                    f2_to_e4m3x2(a0 * PSCALE, a1 * PSCALE);
                *(unsigned short*)(smem + P_OFF + (er0 + 8) * 80 + col) =
                    f2_to_e4m3x2(a2 * PSCALE, a3 * PSCALE);
                if (ab) {
                    *(float2*)&att_s[er0 * ATT_STRIDE + col]       = make_float2(a0, a1);
                    *(float2*)&att_s[(er0 + 8) * ATT_STRIDE + col] = make_float2(a2, a3);
                }
            }
        }
        __syncthreads();

        // ---- att coalesced store: warp = 2 rows x 256B, STG.128 streaming ----
        if (ab) {
#pragma unroll
            for (int k = 0; k < 4; k++) {
                int row = w * 2 + (lane >> 4) + k * 16;
                int c4  = (lane & 15) * 4;
                float4 v = *(const float4*)&att_s[row * ATT_STRIDE + c4];
                __stcs((float4*)&ab[(long)row * NN + j0 + c4], v);
            }
        }

        // ---- AV(t): O += P'(t) @ V^T(stage t%3) ----
        {
            uint32_t vst = sb + V_OFF + (t % 3) * V_STAGE;
            uint32_t pA  = sb + P_OFF
                + (avi * 32 + (lane & 7) + ((lane >> 3) & 1) * 8) * 80
                + ((lane >> 4) & 1) * 16;
            uint32_t af[2][2][4];
#pragma unroll
            for (int mt = 0; mt < 2; mt++) {
                ldsm4(af[mt][0], pA + mt * 16 * 80);
                ldsm4(af[mt][1], pA + mt * 16 * 80 + 32);
            }
#pragma unroll
            for (int kk = 0; kk < 2; kk++) {
#pragma unroll
                for (int ntg = 0; ntg < 4; ntg++) {
                    uint32_t bv[4];
                    uint32_t baddr = vst
                        + (avc * 64 + ntg * 16 + (lane & 7) + ((lane >> 4) & 1) * 8) * 80
                        + ((lane >> 3) & 1) * 16 + kk * 32;
                    ldsm4(bv, baddr);
                    mma_f8(acc[0][ntg * 2],     af[0][kk], bv[0], bv[1]);
                    mma_f8(acc[0][ntg * 2 + 1], af[0][kk], bv[2], bv[3]);
                    mma_f8(acc[1][ntg * 2],     af[1][kk], bv[0], bv[1]);
                    mma_f8(acc[1][ntg * 2 + 1], af[1][kk], bv[2], bv[3]);
                }
            }
        }

        // ---- prefetch V(t+2), K2(t+2) ----
        if (t + 2 < 64) {
            uint32_t vst = sb + V_OFF + ((t + 2) % 3) * V_STAGE;
            const uint8_t* vsrc = vtg + (t + 2) * 64;
#pragma unroll
            for (int p = 0; p < 4; p++) {
                int idx = tid + p * 256;
                int c = idx >> 2, ch = idx & 3;
                CP16(vst + c * 80 + ch * 16, vsrc + (long)c * NN + ch * 16);
            }
            uint32_t k2t = sb + K2_OFF + ((t + 2) & 3) * K2_STAGE;
            const __half* ksrc = kg + (t + 2) * 64 * DD;
            int r = tid >> 2, ch = tid & 3;
            CP16(k2t + r * 80 + ch * 16, ksrc + r * DD + ch * 8);
        }
        CP_COMMIT();
    }

    // ---- epilogue: y = acc*(gamma/PSCALE) + x ----
    const float g = gamma[0] * (1.0f / PSCALE);
    const float* xb = x + ((long)b * NN + i0) * CC;
    float* yb = y + ((long)b * NN + i0) * CC;
#pragma unroll
    for (int mt = 0; mt < 2; mt++) {
        int r0 = avi * 32 + mt * 16 + (lane >> 2);
#pragma unroll
        for (int nt = 0; nt < 8; nt++) {
            int c = avc * 64 + nt * 8 + ((lane & 3) << 1);
            float2 x0 = *(const float2*)&xb[(long)r0 * CC + c];
            float2 x1 = *(const float2*)&xb[(long)(r0 + 8) * CC + c];
            float2 o0, o1;
            o0.x = acc[mt][nt][0] * g + x0.x;  o0.y = acc[mt][nt][1] * g + x0.y;
            o1.x = acc[mt][nt][2] * g + x1.x;  o1.y = acc[mt][nt][3] * g + x1.y;
            *(float2*)&yb[(long)r0 * CC + c]       = o0;
            *(float2*)&yb[(long)(r0 + 8) * CC + c] = o1;
        }
    }
}

// ---------------------------------------------------------------------------
extern "C" void kernel_launch(void* const* d_in, const int* in_sizes, int n_in,
                              void* d_out, int out_size)
{
    const float* x     = (const float*)d_in[0];
    const float* Wq    = (const float*)d_in[1];
    const float* bq    = (const float*)d_in[2];
    const float* Wk    = (const float*)d_in[3];
    const float* bk    = (const float*)d_in[4];
    const float* Wv    = (const float*)d_in[5];
    const float* bv    = (const float*)d_in[6];
    const float* gamma = (const float*)d_in[7];
    float* y = (float*)d_out;

    const long ATT_E = (long)BN * NN * NN;
    float* att_out = 0;
    if ((long)out_size == (long)OUT_E + ATT_E) att_out = y + OUT_E;

    cudaFuncSetAttribute(attn_kernel, cudaFuncAttributeMaxDynamicSharedMemorySize,
                         SMEM_ATTN);

    qkv16_kernel<<<BN * NN / 64, 256>>>(x, Wq, bq, Wk, bk, Wv, bv);
    sum_kernel<<<dim3(NN / 32, BN), 128>>>();
    attn_kernel<<<dim3(NN / 64, BN), 256, SMEM_ATTN>>>(x, gamma, att_out, y);
}